// round 13
// baseline (speedup 1.0000x reference)
#include <cuda_runtime.h>
#include <cuda_bf16.h>

#define Hh 200
#define Dd 768
#define BSROWS 2048   // B*S
#define SQ 512
#define NB 4
#define HH2 (Hh * Hh)
#define KP 224        // padded K for the H-sized contraction dims (7 * 32)
#define NPW 448       // padded N for W columns (7 * 64)
#define NPU 256       // padded N rows for Ut (4 * 64)
#define NFOLD 8       // o-split for the U fold

// ---------------------------------------------------------------------------
// Scratch (all __device__ globals; no allocation)
// ---------------------------------------------------------------------------
__device__ float g_Upart[NFOLD * HH2];
__device__ __nv_bfloat16 g_xhi[BSROWS * Dd], g_xlo[BSROWS * Dd];
__device__ __nv_bfloat16 g_Wthi[NPW * Dd], g_Wtlo[NPW * Dd];
__device__ __nv_bfloat16 g_Uthi[NPU * KP], g_Utlo[NPU * KP];
__device__ __nv_bfloat16 g_hhi[BSROWS * KP], g_hlo[BSROWS * KP];
__device__ __nv_bfloat16 g_thi[BSROWS * KP], g_tlo[BSROWS * KP];
__device__ __nv_bfloat16 g_Mhi[BSROWS * KP], g_Mlo[BSROWS * KP];

__device__ __forceinline__ void bsplit(float v, __nv_bfloat16& h,
                                       __nv_bfloat16& l) {
    h = __float2bfloat16(v);
    l = __float2bfloat16(v - __bfloat162float(h));
}

// ---------------------------------------------------------------------------
// Fold partials: Upart[p][i,j] = sum_{o in slice p} U[o,i,j] * W_down[o]
// ---------------------------------------------------------------------------
__global__ void fold_u_kernel(const float* __restrict__ U,
                              const float* __restrict__ W_down) {
    int idx = blockIdx.x * 256 + threadIdx.x;
    if (idx >= HH2) return;
    int o0 = blockIdx.y * 25;
    const float* p = U + (size_t)o0 * HH2 + idx;
    const float* w = W_down + o0;
    float a0 = 0.f, a1 = 0.f, a2 = 0.f, a3 = 0.f, a4 = 0.f;
#pragma unroll
    for (int u = 0; u < 25; u += 5) {
        a0 = fmaf(p[(size_t)(u + 0) * HH2], __ldg(w + u + 0), a0);
        a1 = fmaf(p[(size_t)(u + 1) * HH2], __ldg(w + u + 1), a1);
        a2 = fmaf(p[(size_t)(u + 2) * HH2], __ldg(w + u + 2), a2);
        a3 = fmaf(p[(size_t)(u + 3) * HH2], __ldg(w + u + 3), a3);
        a4 = fmaf(p[(size_t)(u + 4) * HH2], __ldg(w + u + 4), a4);
    }
    g_Upart[(size_t)blockIdx.y * HH2 + idx] = ((a0 + a1) + (a2 + a3)) + a4;
}

// ---------------------------------------------------------------------------
// x [2048,768] fp32 -> hi/lo bf16 planes. 16 elems/thread, 4 front-batched
// LDG.128 (MLP=4), grid stays at 384 blocks (>=148).
// ---------------------------------------------------------------------------
__global__ void split_x_kernel(const float* __restrict__ x) {
    int i = blockIdx.x * blockDim.x + threadIdx.x;  // 16-float chunk id
    if (i >= BSROWS * Dd / 16) return;
    const float4* p = (const float4*)x + (size_t)i * 4;
    float4 f[4];
#pragma unroll
    for (int j = 0; j < 4; ++j) f[j] = p[j];
#pragma unroll
    for (int j = 0; j < 2; ++j) {
        float v[8] = {f[2 * j].x,     f[2 * j].y,     f[2 * j].z,
                      f[2 * j].w,     f[2 * j + 1].x, f[2 * j + 1].y,
                      f[2 * j + 1].z, f[2 * j + 1].w};
        union { __nv_bfloat16 h[8]; uint4 u; } H, L;
#pragma unroll
        for (int k = 0; k < 8; ++k) bsplit(v[k], H.h[k], L.h[k]);
        *(uint4*)(g_xhi + (size_t)i * 16 + j * 8) = H.u;
        *(uint4*)(g_xlo + (size_t)i * 16 + j * 8) = L.u;
    }
}

// ---------------------------------------------------------------------------
// W transpose+split: [768,200]x2 -> [448,768] hi/lo, smem-tiled.
// ---------------------------------------------------------------------------
__global__ void split_w_kernel(const float* __restrict__ Wh,
                               const float* __restrict__ Wt) {
    __shared__ float tile[32][33];
    const int k0 = blockIdx.x * 32, n0 = blockIdx.y * 32;
    const int tx = threadIdx.x, ty = threadIdx.y;
    const int n = n0 + tx;
#pragma unroll
    for (int j = 0; j < 4; ++j) {
        int k = k0 + ty + j * 8;
        float v = 0.f;
        if (n < Hh) v = Wh[(size_t)k * Hh + n];
        else if (n < 2 * Hh) v = Wt[(size_t)k * Hh + (n - Hh)];
        tile[tx][ty + j * 8] = v;  // [n_local][k_local]
    }
    __syncthreads();
#pragma unroll
    for (int j = 0; j < 4; ++j) {
        int nn = n0 + ty + j * 8, k = k0 + tx;
        float v = tile[ty + j * 8][tx];
        __nv_bfloat16 h, l;
        bsplit(v, h, l);
        g_Wthi[(size_t)nn * Dd + k] = h;
        g_Wtlo[(size_t)nn * Dd + k] = l;
    }
}

// ---------------------------------------------------------------------------
// Ut transpose+split (+reduce fold partials) AND head-pad zeroing (merged).
// grid (7, 9), block (32, 8). y<8: transpose tiles; y==8: zero pads.
// ---------------------------------------------------------------------------
__global__ void split_ut_pad_kernel() {
    if (blockIdx.y == 8) {
        int tid = threadIdx.y * 32 + threadIdx.x;
        const uint4 z = make_uint4(0, 0, 0, 0);
        for (int i = blockIdx.x * 256 + tid; i < BSROWS * 3; i += 7 * 256) {
            int row = i / 3, c = Hh + (i % 3) * 8;
            *(uint4*)(g_hhi + (size_t)row * KP + c) = z;
            *(uint4*)(g_hlo + (size_t)row * KP + c) = z;
        }
        return;
    }
    __shared__ float tile[32][33];
    const int k0 = blockIdx.x * 32, n0 = blockIdx.y * 32;
    const int tx = threadIdx.x, ty = threadIdx.y;
    const int n = n0 + tx;
#pragma unroll
    for (int j = 0; j < 4; ++j) {
        int k = k0 + ty + j * 8;
        float v = 0.f;
        if (n < Hh && k < Hh) {
            size_t o = (size_t)k * Hh + n;
#pragma unroll
            for (int p = 0; p < NFOLD; ++p) v += g_Upart[p * HH2 + o];
        }
        tile[tx][ty + j * 8] = v;
    }
    __syncthreads();
#pragma unroll
    for (int j = 0; j < 4; ++j) {
        int nn = n0 + ty + j * 8, k = k0 + tx;
        float v = tile[ty + j * 8][tx];
        __nv_bfloat16 h, l;
        bsplit(v, h, l);
        g_Uthi[(size_t)nn * KP + k] = h;
        g_Utlo[(size_t)nn * KP + k] = l;
    }
}

// ---------------------------------------------------------------------------
// MMA / async-copy primitives
// ---------------------------------------------------------------------------
__device__ __forceinline__ void ldsm4(unsigned r[4], unsigned a) {
    asm volatile(
        "ldmatrix.sync.aligned.m8n8.x4.shared.b16 {%0,%1,%2,%3}, [%4];\n"
        : "=r"(r[0]), "=r"(r[1]), "=r"(r[2]), "=r"(r[3])
        : "r"(a));
}
__device__ __forceinline__ void mma_bf16(float c[4], const unsigned a[4],
                                         const unsigned b[2]) {
    asm volatile(
        "mma.sync.aligned.m16n8k16.row.col.f32.bf16.bf16.f32 "
        "{%0,%1,%2,%3}, {%4,%5,%6,%7}, {%8,%9}, {%0,%1,%2,%3};\n"
        : "+f"(c[0]), "+f"(c[1]), "+f"(c[2]), "+f"(c[3])
        : "r"(a[0]), "r"(a[1]), "r"(a[2]), "r"(a[3]), "r"(b[0]), "r"(b[1]));
}
__device__ __forceinline__ void cp16(unsigned saddr, const void* g) {
    asm volatile("cp.async.cg.shared.global [%0], [%1], 16;\n" ::"r"(saddr),
                 "l"(g));
}
#define CP_COMMIT() asm volatile("cp.async.commit_group;\n" ::: "memory")
#define CP_WAIT2()  asm volatile("cp.async.wait_group 2;\n" ::: "memory")

// XOR swizzle for 64B rows.
__device__ __forceinline__ unsigned swz(int row, int c) {
    return (unsigned)(row * 64 + ((c ^ ((row >> 1) & 3)) << 4));
}

// ---------------------------------------------------------------------------
// Unified bf16x3 MMA GEMM, 4-stage cp.async pipeline, and THREE independent
// accumulator sets (one per bf16x3 pass) -> 12 independent HMMA chains/warp.
// A planes [m][k] (lda), B planes [n][k] (ldb); all zero-padded.
// MODE 0: proj epilogue (bias+relu -> split to g_h*/g_t*)
// MODE 1: gemm_m epilogue (split to g_M*, zero k-pad)
// MODE 2: scores epilogue ((v + bd) / sqrt(200) -> fp32 out, batched by z)
// ---------------------------------------------------------------------------
#define GEMM_SMEM 65536
template <int MODE>
__global__ __launch_bounds__(256) void mma_gemm_kernel(
    const __nv_bfloat16* __restrict__ Ahi, const __nv_bfloat16* __restrict__ Alo,
    int lda,
    const __nv_bfloat16* __restrict__ Bhi, const __nv_bfloat16* __restrict__ Blo,
    int ldb, int ktiles,
    const float* __restrict__ bias_h, const float* __restrict__ bias_t,
    float* __restrict__ outf, const float* __restrict__ bdown) {
    constexpr int BM = 64;
    constexpr int ABYTES = BM * 64;
    constexpr int BBYTES = 64 * 64;
    constexpr int STAGE = 2 * ABYTES + 2 * BBYTES;  // 16384
    constexpr int NSTAGE = 4;
    extern __shared__ __align__(16) unsigned char smem[];  // 64KB dynamic

    const int t = threadIdx.x;
    const int lane = t & 31, warp = t >> 5;
    const int m0 = blockIdx.y * BM;
    const int n0 = blockIdx.x * 64;
    const int wm = (warp & 1) * 32, wn = (warp >> 1) * 16;

    if (MODE == 2) {
        size_t ofs = (size_t)blockIdx.z * SQ;
        Ahi += ofs * lda; Alo += ofs * lda;
        Bhi += ofs * ldb; Blo += ofs * ldb;
    }

    const __nv_bfloat16* aptr[2];
    unsigned aoff[2];
#pragma unroll
    for (int i = 0; i < 2; ++i) {
        int ca = t + i * 256;
        int pl = ca / (BM * 4);
        int rem = ca - pl * (BM * 4);
        int row = rem >> 2, c = rem & 3;
        aptr[i] = (pl ? Alo : Ahi) + (size_t)(m0 + row) * lda + c * 8;
        aoff[i] = pl * ABYTES + swz(row, c);
    }
    const __nv_bfloat16* bptr[2];
    unsigned boff[2];
#pragma unroll
    for (int i = 0; i < 2; ++i) {
        int cb = t + i * 256;
        int pl = cb >> 8;
        int rem = cb & 255;
        int row = rem >> 2, c = rem & 3;
        bptr[i] = (pl ? Blo : Bhi) + (size_t)(n0 + row) * ldb + c * 8;
        boff[i] = 2 * ABYTES + pl * BBYTES + swz(row, c);
    }

    const unsigned sbase = (unsigned)__cvta_generic_to_shared(smem);

    auto issue = [&](int kt) {
        unsigned so = sbase + (kt % NSTAGE) * STAGE;
#pragma unroll
        for (int i = 0; i < 2; ++i) cp16(so + aoff[i], aptr[i] + kt * 32);
#pragma unroll
        for (int i = 0; i < 2; ++i) cp16(so + boff[i], bptr[i] + kt * 32);
    };

    // three independent accumulator sets (one per bf16x3 pass)
    float acc[3][2][2][4];
#pragma unroll
    for (int p = 0; p < 3; ++p)
#pragma unroll
        for (int mi = 0; mi < 2; ++mi)
#pragma unroll
            for (int ni = 0; ni < 2; ++ni)
#pragma unroll
                for (int r = 0; r < 4; ++r) acc[p][mi][ni][r] = 0.f;

    auto compute = [&](int stg) {
        unsigned bb = sbase + stg * STAGE;
#pragma unroll
        for (int s = 0; s < 2; ++s) {
            unsigned ah[2][4], al[2][4], bh2[2][2], bl2[2][2];
            {
                int row0 = wm + (lane & 15);
                int c = 2 * s + (lane >> 4);
#pragma unroll
                for (int mi = 0; mi < 2; ++mi) {
                    unsigned sa = swz(row0 + mi * 16, c);
                    ldsm4(ah[mi], bb + sa);
                    ldsm4(al[mi], bb + ABYTES + sa);
                }
            }
            {
                int rbase = wn + (lane & 7) + ((lane >> 4) << 3);
                int c = 2 * s + ((lane >> 3) & 1);
                unsigned sb = swz(rbase, c);
                unsigned tmp[4];
                ldsm4(tmp, bb + 2 * ABYTES + sb);
                bh2[0][0] = tmp[0]; bh2[0][1] = tmp[1];
                bh2[1][0] = tmp[2]; bh2[1][1] = tmp[3];
                ldsm4(tmp, bb + 2 * ABYTES + BBYTES + sb);
                bl2[0][0] = tmp[0]; bl2[0][1] = tmp[1];
                bl2[1][0] = tmp[2]; bl2[1][1] = tmp[3];
            }
            // interleave the 3 passes -> independent accumulator chains
#pragma unroll
            for (int mi = 0; mi < 2; ++mi)
#pragma unroll
                for (int ni = 0; ni < 2; ++ni) {
                    mma_bf16(acc[0][mi][ni], ah[mi], bh2[ni]);
                    mma_bf16(acc[1][mi][ni], ah[mi], bl2[ni]);
                    mma_bf16(acc[2][mi][ni], al[mi], bh2[ni]);
                }
        }
    };

    // prologue: 3 stages in flight (ktiles >= 3 always: 7 or 24)
    issue(0); CP_COMMIT();
    issue(1); CP_COMMIT();
    issue(2); CP_COMMIT();
    CP_WAIT2();          // stage 0 complete
    __syncthreads();

#pragma unroll 1
    for (int kt = 0; kt < ktiles; ++kt) {
        compute(kt % NSTAGE);
        if (kt + 3 < ktiles) issue(kt + 3);
        CP_COMMIT();     // (possibly empty group keeps the count aligned)
        CP_WAIT2();      // stage kt+1 complete
        __syncthreads();
    }

    const float rs = 0.070710678118654752f;
    float bd = 0.f;
    if (MODE == 2) bd = __ldg(bdown);

#pragma unroll
    for (int mi = 0; mi < 2; ++mi) {
#pragma unroll
        for (int ni = 0; ni < 2; ++ni) {
#pragma unroll
            for (int rp = 0; rp < 2; ++rp) {
                int row = m0 + wm + mi * 16 + (lane >> 2) + rp * 8;
                int col = n0 + wn + ni * 8 + 2 * (lane & 3);
                float v0 = acc[0][mi][ni][rp * 2] + acc[1][mi][ni][rp * 2] +
                           acc[2][mi][ni][rp * 2];
                float v1 = acc[0][mi][ni][rp * 2 + 1] +
                           acc[1][mi][ni][rp * 2 + 1] +
                           acc[2][mi][ni][rp * 2 + 1];
                if (MODE == 0) {
                    if (col < Hh) {
                        v0 = fmaxf(v0 + __ldg(&bias_h[col]), 0.f);
                        v1 = fmaxf(v1 + __ldg(&bias_h[col + 1]), 0.f);
                        __nv_bfloat16 h0, l0, h1, l1;
                        bsplit(v0, h0, l0);
                        bsplit(v1, h1, l1);
                        size_t o = (size_t)row * KP + col;
                        *(__nv_bfloat162*)(g_hhi + o) = __halves2bfloat162(h0, h1);
                        *(__nv_bfloat162*)(g_hlo + o) = __halves2bfloat162(l0, l1);
                    } else {
                        int c = col - Hh;
                        if (c < KP) {
                            if (col < 2 * Hh) {
                                v0 = fmaxf(v0 + __ldg(&bias_t[c]), 0.f);
                                v1 = fmaxf(v1 + __ldg(&bias_t[c + 1]), 0.f);
                            } else {
                                v0 = 0.f;
                                v1 = 0.f;
                            }
                            __nv_bfloat16 h0, l0, h1, l1;
                            bsplit(v0, h0, l0);
                            bsplit(v1, h1, l1);
                            size_t o = (size_t)row * KP + c;
                            *(__nv_bfloat162*)(g_thi + o) =
                                __halves2bfloat162(h0, h1);
                            *(__nv_bfloat162*)(g_tlo + o) =
                                __halves2bfloat162(l0, l1);
                        }
                    }
                } else if (MODE == 1) {
                    if (col < KP) {
                        if (col >= Hh) { v0 = 0.f; v1 = 0.f; }
                        __nv_bfloat16 h0, l0, h1, l1;
                        bsplit(v0, h0, l0);
                        bsplit(v1, h1, l1);
                        size_t o = (size_t)row * KP + col;
                        *(__nv_bfloat162*)(g_Mhi + o) = __halves2bfloat162(h0, h1);
                        *(__nv_bfloat162*)(g_Mlo + o) = __halves2bfloat162(l0, l1);
                    }
                } else {
                    float2 o;
                    o.x = (v0 + bd) * rs;
                    o.y = (v1 + bd) * rs;
                    *(float2*)(outf + (size_t)blockIdx.z * SQ * SQ +
                               (size_t)row * SQ + col) = o;
                }
            }
        }
    }
}

// ---------------------------------------------------------------------------
// Inputs (metadata order): x, W_head, b_head, W_tail, b_tail, U, W_down, b_down
// ---------------------------------------------------------------------------
extern "C" void kernel_launch(void* const* d_in, const int* in_sizes, int n_in,
                              void* d_out, int out_size) {
    const float* x      = (const float*)d_in[0];
    const float* W_head = (const float*)d_in[1];
    const float* b_head = (const float*)d_in[2];
    const float* W_tail = (const float*)d_in[3];
    const float* b_tail = (const float*)d_in[4];
    const float* U      = (const float*)d_in[5];
    const float* W_down = (const float*)d_in[6];
    const float* b_down = (const float*)d_in[7];
    float* out = (float*)d_out;

    static __nv_bfloat16 *p_xhi, *p_xlo, *p_Wthi, *p_Wtlo, *p_Uthi, *p_Utlo;
    static __nv_bfloat16 *p_hhi, *p_hlo, *p_thi, *p_tlo, *p_Mhi, *p_Mlo;
    static cudaStream_t s1, s2;
    static cudaEvent_t e_fork, e_join1, e_join2;
    static bool init = false;
    if (!init) {
        cudaGetSymbolAddress((void**)&p_xhi, g_xhi);
        cudaGetSymbolAddress((void**)&p_xlo, g_xlo);
        cudaGetSymbolAddress((void**)&p_Wthi, g_Wthi);
        cudaGetSymbolAddress((void**)&p_Wtlo, g_Wtlo);
        cudaGetSymbolAddress((void**)&p_Uthi, g_Uthi);
        cudaGetSymbolAddress((void**)&p_Utlo, g_Utlo);
        cudaGetSymbolAddress((void**)&p_hhi, g_hhi);
        cudaGetSymbolAddress((void**)&p_hlo, g_hlo);
        cudaGetSymbolAddress((void**)&p_thi, g_thi);
        cudaGetSymbolAddress((void**)&p_tlo, g_tlo);
        cudaGetSymbolAddress((void**)&p_Mhi, g_Mhi);
        cudaGetSymbolAddress((void**)&p_Mlo, g_Mlo);
        cudaFuncSetAttribute(mma_gemm_kernel<0>,
                             cudaFuncAttributeMaxDynamicSharedMemorySize,
                             GEMM_SMEM);
        cudaFuncSetAttribute(mma_gemm_kernel<1>,
                             cudaFuncAttributeMaxDynamicSharedMemorySize,
                             GEMM_SMEM);
        cudaFuncSetAttribute(mma_gemm_kernel<2>,
                             cudaFuncAttributeMaxDynamicSharedMemorySize,
                             GEMM_SMEM);
        cudaStreamCreateWithFlags(&s1, cudaStreamNonBlocking);
        cudaStreamCreateWithFlags(&s2, cudaStreamNonBlocking);
        cudaEventCreateWithFlags(&e_fork, cudaEventDisableTiming);
        cudaEventCreateWithFlags(&e_join1, cudaEventDisableTiming);
        cudaEventCreateWithFlags(&e_join2, cudaEventDisableTiming);
        init = true;
    }

    // fork
    cudaEventRecord(e_fork, 0);
    cudaStreamWaitEvent(s1, e_fork, 0);
    cudaStreamWaitEvent(s2, e_fork, 0);

    // s1: U fold chain + head pads (needed before gemm_m)
    fold_u_kernel<<<dim3((HH2 + 255) / 256, NFOLD), 256, 0, s1>>>(U, W_down);
    split_ut_pad_kernel<<<dim3(KP / 32, 9), dim3(32, 8), 0, s1>>>();
    cudaEventRecord(e_join1, s1);

    // s2: W split (needed before proj)
    split_w_kernel<<<dim3(Dd / 32, NPW / 32), dim3(32, 8), 0, s2>>>(W_head,
                                                                    W_tail);
    cudaEventRecord(e_join2, s2);

    // main: x split, then pipelined GEMM chain
    split_x_kernel<<<BSROWS * Dd / 16 / 256, 256>>>(x);

    cudaStreamWaitEvent(0, e_join2, 0);  // proj needs W planes
    mma_gemm_kernel<0><<<dim3(NPW / 64, BSROWS / 64), 256, GEMM_SMEM>>>(
        p_xhi, p_xlo, Dd, p_Wthi, p_Wtlo, Dd, Dd / 32, b_head, b_tail,
        nullptr, nullptr);

    cudaStreamWaitEvent(0, e_join1, 0);  // gemm_m needs Ut + head pads
    mma_gemm_kernel<1><<<dim3(NPU / 64, BSROWS / 64), 256, GEMM_SMEM>>>(
        p_hhi, p_hlo, KP, p_Uthi, p_Utlo, KP, KP / 32, nullptr, nullptr,
        nullptr, nullptr);

    mma_gemm_kernel<2><<<dim3(SQ / 64, SQ / 64, NB), 256, GEMM_SMEM>>>(
        p_Mhi, p_Mlo, KP, p_thi, p_tlo, KP, KP / 32, nullptr, nullptr, out,
        b_down);
}

// round 14
// speedup vs baseline: 1.2092x; 1.2092x over previous
#include <cuda_runtime.h>
#include <cuda_bf16.h>

#define Hh 200
#define Dd 768
#define BSROWS 2048   // B*S
#define SQ 512
#define NB 4
#define HH2 (Hh * Hh)
#define KP 224        // padded K for the H-sized contraction dims (7 * 32)
#define NPW 448       // padded N for W columns (7 * 64)
#define NPU 256       // padded N rows for Ut (4 * 64)
#define NFOLD 8       // o-split for the U fold

// block ranges in prep_kernel
#define FOLD_BLKS 157          // blocks per o-slice
#define PREP_FOLD (FOLD_BLKS * NFOLD)          // 1256
#define PREP_W    (PREP_FOLD + 24 * 14)        // +336 = 1592
#define PREP_X    (PREP_W + 768)               // +768 = 2360

// ---------------------------------------------------------------------------
// Scratch (all __device__ globals; no allocation)
// ---------------------------------------------------------------------------
__device__ float g_Upart[NFOLD * HH2];
__device__ __nv_bfloat16 g_xhi[BSROWS * Dd], g_xlo[BSROWS * Dd];
__device__ __nv_bfloat16 g_Wthi[NPW * Dd], g_Wtlo[NPW * Dd];
__device__ __nv_bfloat16 g_Uthi[NPU * KP], g_Utlo[NPU * KP];
__device__ __nv_bfloat16 g_hhi[BSROWS * KP], g_hlo[BSROWS * KP];
__device__ __nv_bfloat16 g_thi[BSROWS * KP], g_tlo[BSROWS * KP];
__device__ __nv_bfloat16 g_Mhi[BSROWS * KP], g_Mlo[BSROWS * KP];

__device__ __forceinline__ void bsplit(float v, __nv_bfloat16& h,
                                       __nv_bfloat16& l) {
    h = __float2bfloat16(v);
    l = __float2bfloat16(v - __bfloat162float(h));
}

// ---------------------------------------------------------------------------
// prep_kernel: fold partials  ∪  W transpose+split  ∪  x split.
// All three are independent; dispatched by blockIdx.x range. Bodies are
// byte-identical to the proven standalone kernels.
// ---------------------------------------------------------------------------
__global__ void prep_kernel(const float* __restrict__ U,
                            const float* __restrict__ W_down,
                            const float* __restrict__ Wh,
                            const float* __restrict__ Wt,
                            const float* __restrict__ x) {
    __shared__ float tile[32][33];
    const int bid = blockIdx.x;
    const int t = threadIdx.x;

    if (bid < PREP_FOLD) {
        // ---- fold: Upart[p][i,j] = sum_{o in slice p} U[o,i,j]*W_down[o]
        int p = bid / FOLD_BLKS, blk = bid - p * FOLD_BLKS;
        int idx = blk * 256 + t;
        if (idx >= HH2) return;
        int o0 = p * 25;
        const float* pp = U + (size_t)o0 * HH2 + idx;
        const float* w = W_down + o0;
        float a0 = 0.f, a1 = 0.f, a2 = 0.f, a3 = 0.f, a4 = 0.f;
#pragma unroll
        for (int u = 0; u < 25; u += 5) {
            a0 = fmaf(pp[(size_t)(u + 0) * HH2], __ldg(w + u + 0), a0);
            a1 = fmaf(pp[(size_t)(u + 1) * HH2], __ldg(w + u + 1), a1);
            a2 = fmaf(pp[(size_t)(u + 2) * HH2], __ldg(w + u + 2), a2);
            a3 = fmaf(pp[(size_t)(u + 3) * HH2], __ldg(w + u + 3), a3);
            a4 = fmaf(pp[(size_t)(u + 4) * HH2], __ldg(w + u + 4), a4);
        }
        g_Upart[(size_t)p * HH2 + idx] = ((a0 + a1) + (a2 + a3)) + a4;
    } else if (bid < PREP_W) {
        // ---- W transpose+split (smem-tiled)
        int sub = bid - PREP_FOLD;
        const int k0 = (sub % 24) * 32, n0 = (sub / 24) * 32;
        const int tx = t & 31, ty = t >> 5;
        const int n = n0 + tx;
#pragma unroll
        for (int j = 0; j < 4; ++j) {
            int k = k0 + ty + j * 8;
            float v = 0.f;
            if (n < Hh) v = Wh[(size_t)k * Hh + n];
            else if (n < 2 * Hh) v = Wt[(size_t)k * Hh + (n - Hh)];
            tile[tx][ty + j * 8] = v;
        }
        __syncthreads();
#pragma unroll
        for (int j = 0; j < 4; ++j) {
            int nn = n0 + ty + j * 8, k = k0 + tx;
            float v = tile[ty + j * 8][tx];
            __nv_bfloat16 h, l;
            bsplit(v, h, l);
            g_Wthi[(size_t)nn * Dd + k] = h;
            g_Wtlo[(size_t)nn * Dd + k] = l;
        }
    } else {
        // ---- x split: 8 elems/thread, coalesced (proven shape)
        int i = (bid - PREP_W) * 256 + t;
        const float4* p = (const float4*)x + (size_t)i * 2;
        float4 f0 = p[0], f1 = p[1];
        float v[8] = {f0.x, f0.y, f0.z, f0.w, f1.x, f1.y, f1.z, f1.w};
        union { __nv_bfloat16 h[8]; uint4 u; } H, L;
#pragma unroll
        for (int j = 0; j < 8; ++j) bsplit(v[j], H.h[j], L.h[j]);
        *(uint4*)(g_xhi + (size_t)i * 8) = H.u;
        *(uint4*)(g_xlo + (size_t)i * 8) = L.u;
    }
}

// ---------------------------------------------------------------------------
// MMA / async-copy primitives
// ---------------------------------------------------------------------------
__device__ __forceinline__ void ldsm4(unsigned r[4], unsigned a) {
    asm volatile(
        "ldmatrix.sync.aligned.m8n8.x4.shared.b16 {%0,%1,%2,%3}, [%4];\n"
        : "=r"(r[0]), "=r"(r[1]), "=r"(r[2]), "=r"(r[3])
        : "r"(a));
}
__device__ __forceinline__ void mma_bf16(float c[4], const unsigned a[4],
                                         const unsigned b[2]) {
    asm volatile(
        "mma.sync.aligned.m16n8k16.row.col.f32.bf16.bf16.f32 "
        "{%0,%1,%2,%3}, {%4,%5,%6,%7}, {%8,%9}, {%0,%1,%2,%3};\n"
        : "+f"(c[0]), "+f"(c[1]), "+f"(c[2]), "+f"(c[3])
        : "r"(a[0]), "r"(a[1]), "r"(a[2]), "r"(a[3]), "r"(b[0]), "r"(b[1]));
}
__device__ __forceinline__ void cp16(unsigned saddr, const void* g) {
    asm volatile("cp.async.cg.shared.global [%0], [%1], 16;\n" ::"r"(saddr),
                 "l"(g));
}
#define CP_COMMIT() asm volatile("cp.async.commit_group;\n" ::: "memory")
#define CP_WAIT2()  asm volatile("cp.async.wait_group 2;\n" ::: "memory")

// XOR swizzle for 64B rows.
__device__ __forceinline__ unsigned swz(int row, int c) {
    return (unsigned)(row * 64 + ((c ^ ((row >> 1) & 3)) << 4));
}

// ---------------------------------------------------------------------------
// Shared GEMM body (R12-proven): bf16x3 MMA, 4-stage cp.async pipeline.
// A planes [m][k] (lda), B planes [n][k] (ldb); all zero-padded.
// ---------------------------------------------------------------------------
#define GEMM_SMEM 65536
template <int MODE>
__device__ __forceinline__ void gemm_body(
    int m0, int n0, int bz, unsigned char* smem,
    const __nv_bfloat16* Ahi, const __nv_bfloat16* Alo, int lda,
    const __nv_bfloat16* Bhi, const __nv_bfloat16* Blo, int ldb, int ktiles,
    const float* bias_h, const float* bias_t, float* outf,
    const float* bdown) {
    constexpr int BM = 64;
    constexpr int ABYTES = BM * 64;
    constexpr int BBYTES = 64 * 64;
    constexpr int STAGE = 2 * ABYTES + 2 * BBYTES;  // 16384
    constexpr int NSTAGE = 4;

    const int t = threadIdx.x;
    const int lane = t & 31, warp = t >> 5;
    const int wm = (warp & 1) * 32, wn = (warp >> 1) * 16;

    if (MODE == 2) {
        size_t ofs = (size_t)bz * SQ;
        Ahi += ofs * lda; Alo += ofs * lda;
        Bhi += ofs * ldb; Blo += ofs * ldb;
    }

    const __nv_bfloat16* aptr[2];
    unsigned aoff[2];
#pragma unroll
    for (int i = 0; i < 2; ++i) {
        int ca = t + i * 256;
        int pl = ca / (BM * 4);
        int rem = ca - pl * (BM * 4);
        int row = rem >> 2, c = rem & 3;
        aptr[i] = (pl ? Alo : Ahi) + (size_t)(m0 + row) * lda + c * 8;
        aoff[i] = pl * ABYTES + swz(row, c);
    }
    const __nv_bfloat16* bptr[2];
    unsigned boff[2];
#pragma unroll
    for (int i = 0; i < 2; ++i) {
        int cb = t + i * 256;
        int pl = cb >> 8;
        int rem = cb & 255;
        int row = rem >> 2, c = rem & 3;
        bptr[i] = (pl ? Blo : Bhi) + (size_t)(n0 + row) * ldb + c * 8;
        boff[i] = 2 * ABYTES + pl * BBYTES + swz(row, c);
    }

    const unsigned sbase = (unsigned)__cvta_generic_to_shared(smem);

    auto issue = [&](int kt) {
        unsigned so = sbase + (kt % NSTAGE) * STAGE;
#pragma unroll
        for (int i = 0; i < 2; ++i) cp16(so + aoff[i], aptr[i] + kt * 32);
#pragma unroll
        for (int i = 0; i < 2; ++i) cp16(so + boff[i], bptr[i] + kt * 32);
    };

    float acc[2][2][4];
#pragma unroll
    for (int mi = 0; mi < 2; ++mi)
#pragma unroll
        for (int ni = 0; ni < 2; ++ni)
#pragma unroll
            for (int r = 0; r < 4; ++r) acc[mi][ni][r] = 0.f;

    auto compute = [&](int stg) {
        unsigned bb = sbase + stg * STAGE;
#pragma unroll
        for (int s = 0; s < 2; ++s) {
            unsigned ah[2][4], al[2][4], bh2[2][2], bl2[2][2];
            {
                int row0 = wm + (lane & 15);
                int c = 2 * s + (lane >> 4);
#pragma unroll
                for (int mi = 0; mi < 2; ++mi) {
                    unsigned sa = swz(row0 + mi * 16, c);
                    ldsm4(ah[mi], bb + sa);
                    ldsm4(al[mi], bb + ABYTES + sa);
                }
            }
            {
                int rbase = wn + (lane & 7) + ((lane >> 4) << 3);
                int c = 2 * s + ((lane >> 3) & 1);
                unsigned sb = swz(rbase, c);
                unsigned tmp[4];
                ldsm4(tmp, bb + 2 * ABYTES + sb);
                bh2[0][0] = tmp[0]; bh2[0][1] = tmp[1];
                bh2[1][0] = tmp[2]; bh2[1][1] = tmp[3];
                ldsm4(tmp, bb + 2 * ABYTES + BBYTES + sb);
                bl2[0][0] = tmp[0]; bl2[0][1] = tmp[1];
                bl2[1][0] = tmp[2]; bl2[1][1] = tmp[3];
            }
#pragma unroll
            for (int mi = 0; mi < 2; ++mi)
#pragma unroll
                for (int ni = 0; ni < 2; ++ni)
                    mma_bf16(acc[mi][ni], ah[mi], bh2[ni]);
#pragma unroll
            for (int mi = 0; mi < 2; ++mi)
#pragma unroll
                for (int ni = 0; ni < 2; ++ni)
                    mma_bf16(acc[mi][ni], ah[mi], bl2[ni]);
#pragma unroll
            for (int mi = 0; mi < 2; ++mi)
#pragma unroll
                for (int ni = 0; ni < 2; ++ni)
                    mma_bf16(acc[mi][ni], al[mi], bh2[ni]);
        }
    };

    issue(0); CP_COMMIT();
    issue(1); CP_COMMIT();
    issue(2); CP_COMMIT();
    CP_WAIT2();
    __syncthreads();

#pragma unroll 1
    for (int kt = 0; kt < ktiles; ++kt) {
        compute(kt % NSTAGE);
        if (kt + 3 < ktiles) issue(kt + 3);
        CP_COMMIT();
        CP_WAIT2();
        __syncthreads();
    }

    const float rs = 0.070710678118654752f;
    float bd = 0.f;
    if (MODE == 2) bd = __ldg(bdown);

#pragma unroll
    for (int mi = 0; mi < 2; ++mi) {
#pragma unroll
        for (int ni = 0; ni < 2; ++ni) {
#pragma unroll
            for (int rp = 0; rp < 2; ++rp) {
                int row = m0 + wm + mi * 16 + (lane >> 2) + rp * 8;
                int col = n0 + wn + ni * 8 + 2 * (lane & 3);
                float v0 = acc[mi][ni][rp * 2];
                float v1 = acc[mi][ni][rp * 2 + 1];
                if (MODE == 0) {
                    if (col < Hh) {
                        v0 = fmaxf(v0 + __ldg(&bias_h[col]), 0.f);
                        v1 = fmaxf(v1 + __ldg(&bias_h[col + 1]), 0.f);
                        __nv_bfloat16 h0, l0, h1, l1;
                        bsplit(v0, h0, l0);
                        bsplit(v1, h1, l1);
                        size_t o = (size_t)row * KP + col;
                        *(__nv_bfloat162*)(g_hhi + o) = __halves2bfloat162(h0, h1);
                        *(__nv_bfloat162*)(g_hlo + o) = __halves2bfloat162(l0, l1);
                    } else {
                        int c = col - Hh;
                        if (c < KP) {
                            if (col < 2 * Hh) {
                                v0 = fmaxf(v0 + __ldg(&bias_t[c]), 0.f);
                                v1 = fmaxf(v1 + __ldg(&bias_t[c + 1]), 0.f);
                            } else {
                                v0 = 0.f;
                                v1 = 0.f;
                            }
                            __nv_bfloat16 h0, l0, h1, l1;
                            bsplit(v0, h0, l0);
                            bsplit(v1, h1, l1);
                            size_t o = (size_t)row * KP + c;
                            *(__nv_bfloat162*)(g_thi + o) =
                                __halves2bfloat162(h0, h1);
                            *(__nv_bfloat162*)(g_tlo + o) =
                                __halves2bfloat162(l0, l1);
                        }
                    }
                } else if (MODE == 1) {
                    if (col < KP) {
                        if (col >= Hh) { v0 = 0.f; v1 = 0.f; }
                        __nv_bfloat16 h0, l0, h1, l1;
                        bsplit(v0, h0, l0);
                        bsplit(v1, h1, l1);
                        size_t o = (size_t)row * KP + col;
                        *(__nv_bfloat162*)(g_Mhi + o) = __halves2bfloat162(h0, h1);
                        *(__nv_bfloat162*)(g_Mlo + o) = __halves2bfloat162(l0, l1);
                    }
                } else {
                    float2 o;
                    o.x = (v0 + bd) * rs;
                    o.y = (v1 + bd) * rs;
                    *(float2*)(outf + (size_t)bz * SQ * SQ +
                               (size_t)row * SQ + col) = o;
                }
            }
        }
    }
}

// ---------------------------------------------------------------------------
// proj ∪ split_ut_pad in one launch.
// bid < 224: proj tile (n0 = (bid%7)*64, m0 = (bid/7)*64)
// bid >= 224: Ut transpose+split / head-pad zero (63 blocks)
// ---------------------------------------------------------------------------
__global__ __launch_bounds__(256) void proj_ut_kernel(
    const __nv_bfloat16* __restrict__ Ahi, const __nv_bfloat16* __restrict__ Alo,
    const __nv_bfloat16* __restrict__ Bhi, const __nv_bfloat16* __restrict__ Blo,
    const float* __restrict__ bias_h, const float* __restrict__ bias_t) {
    extern __shared__ __align__(16) unsigned char smem[];
    __shared__ float tile[32][33];
    const int bid = blockIdx.x;
    const int t = threadIdx.x;

    if (bid < 224) {
        gemm_body<0>((bid / 7) * 64, (bid % 7) * 64, 0, smem, Ahi, Alo, Dd,
                     Bhi, Blo, Dd, Dd / 32, bias_h, bias_t, nullptr, nullptr);
        return;
    }

    // ---- split_ut_pad (63 blocks): bx = sub%7, by = sub/7 (0..8)
    int sub = bid - 224;
    int bx = sub % 7, by = sub / 7;
    if (by == 8) {
        const uint4 z = make_uint4(0, 0, 0, 0);
        for (int i = bx * 256 + t; i < BSROWS * 3; i += 7 * 256) {
            int row = i / 3, c = Hh + (i % 3) * 8;
            *(uint4*)(g_hhi + (size_t)row * KP + c) = z;
            *(uint4*)(g_hlo + (size_t)row * KP + c) = z;
        }
        return;
    }
    const int k0 = bx * 32, n0 = by * 32;
    const int tx = t & 31, ty = t >> 5;
    const int n = n0 + tx;
#pragma unroll
    for (int j = 0; j < 4; ++j) {
        int k = k0 + ty + j * 8;
        float v = 0.f;
        if (n < Hh && k < Hh) {
            size_t o = (size_t)k * Hh + n;
#pragma unroll
            for (int p = 0; p < NFOLD; ++p) v += g_Upart[p * HH2 + o];
        }
        tile[tx][ty + j * 8] = v;
    }
    __syncthreads();
#pragma unroll
    for (int j = 0; j < 4; ++j) {
        int nn = n0 + ty + j * 8, k = k0 + tx;
        float v = tile[ty + j * 8][tx];
        __nv_bfloat16 h, l;
        bsplit(v, h, l);
        g_Uthi[(size_t)nn * KP + k] = h;
        g_Utlo[(size_t)nn * KP + k] = l;
    }
}

// ---------------------------------------------------------------------------
// gemm_m / scores launches (unchanged internals)
// ---------------------------------------------------------------------------
template <int MODE>
__global__ __launch_bounds__(256) void mma_gemm_kernel(
    const __nv_bfloat16* __restrict__ Ahi, const __nv_bfloat16* __restrict__ Alo,
    int lda,
    const __nv_bfloat16* __restrict__ Bhi, const __nv_bfloat16* __restrict__ Blo,
    int ldb, int ktiles, float* __restrict__ outf,
    const float* __restrict__ bdown) {
    extern __shared__ __align__(16) unsigned char smem[];
    gemm_body<MODE>(blockIdx.y * 64, blockIdx.x * 64, blockIdx.z, smem, Ahi,
                    Alo, lda, Bhi, Blo, ldb, ktiles, nullptr, nullptr, outf,
                    bdown);
}

// ---------------------------------------------------------------------------
// Inputs (metadata order): x, W_head, b_head, W_tail, b_tail, U, W_down, b_down
// ---------------------------------------------------------------------------
extern "C" void kernel_launch(void* const* d_in, const int* in_sizes, int n_in,
                              void* d_out, int out_size) {
    const float* x      = (const float*)d_in[0];
    const float* W_head = (const float*)d_in[1];
    const float* b_head = (const float*)d_in[2];
    const float* W_tail = (const float*)d_in[3];
    const float* b_tail = (const float*)d_in[4];
    const float* U      = (const float*)d_in[5];
    const float* W_down = (const float*)d_in[6];
    const float* b_down = (const float*)d_in[7];
    float* out = (float*)d_out;

    static __nv_bfloat16 *p_xhi, *p_xlo, *p_Wthi, *p_Wtlo, *p_Uthi, *p_Utlo;
    static __nv_bfloat16 *p_hhi, *p_hlo, *p_thi, *p_tlo, *p_Mhi, *p_Mlo;
    static bool init = false;
    if (!init) {
        cudaGetSymbolAddress((void**)&p_xhi, g_xhi);
        cudaGetSymbolAddress((void**)&p_xlo, g_xlo);
        cudaGetSymbolAddress((void**)&p_Wthi, g_Wthi);
        cudaGetSymbolAddress((void**)&p_Wtlo, g_Wtlo);
        cudaGetSymbolAddress((void**)&p_Uthi, g_Uthi);
        cudaGetSymbolAddress((void**)&p_Utlo, g_Utlo);
        cudaGetSymbolAddress((void**)&p_hhi, g_hhi);
        cudaGetSymbolAddress((void**)&p_hlo, g_hlo);
        cudaGetSymbolAddress((void**)&p_thi, g_thi);
        cudaGetSymbolAddress((void**)&p_tlo, g_tlo);
        cudaGetSymbolAddress((void**)&p_Mhi, g_Mhi);
        cudaGetSymbolAddress((void**)&p_Mlo, g_Mlo);
        cudaFuncSetAttribute(proj_ut_kernel,
                             cudaFuncAttributeMaxDynamicSharedMemorySize,
                             GEMM_SMEM);
        cudaFuncSetAttribute(mma_gemm_kernel<1>,
                             cudaFuncAttributeMaxDynamicSharedMemorySize,
                             GEMM_SMEM);
        cudaFuncSetAttribute(mma_gemm_kernel<2>,
                             cudaFuncAttributeMaxDynamicSharedMemorySize,
                             GEMM_SMEM);
        init = true;
    }

    // 1) all independent prep in ONE launch (fold ∪ split_w ∪ split_x)
    prep_kernel<<<PREP_X, 256>>>(U, W_down, W_head, W_tail, x);

    // 2) proj ∪ (Ut transpose/split + head pads)
    proj_ut_kernel<<<224 + 63, 256, GEMM_SMEM>>>(p_xhi, p_xlo, p_Wthi,
                                                 p_Wtlo, b_head, b_tail);

    // 3) M = head @ Ueff
    mma_gemm_kernel<1><<<dim3(NPU / 64, BSROWS / 64), 256, GEMM_SMEM>>>(
        p_hhi, p_hlo, KP, p_Uthi, p_Utlo, KP, KP / 32, nullptr, nullptr);

    // 4) scores[b] = (M_b @ tail_b^T + b_down) / sqrt(200)
    mma_gemm_kernel<2><<<dim3(SQ / 64, SQ / 64, NB), 256, GEMM_SMEM>>>(
        p_Mhi, p_Mlo, KP, p_thi, p_tlo, KP, KP / 32, out, b_down);
}

// round 15
// speedup vs baseline: 1.2102x; 1.0009x over previous
#include <cuda_runtime.h>
#include <cuda_bf16.h>

#define Hh 200
#define Dd 768
#define BSROWS 2048   // B*S
#define SQ 512
#define NB 4
#define HH2 (Hh * Hh)
#define KP 224        // padded K for the H-sized contraction dims (7 * 32)
#define NPW 448       // padded N for W columns (7 * 64)
#define NPU 256       // padded N rows for Ut (4 * 64)
#define NFOLD 8       // o-split for the U fold

// block ranges in prep_kernel
#define FOLD_BLKS 157          // blocks per o-slice
#define PREP_FOLD (FOLD_BLKS * NFOLD)          // 1256
#define PREP_W    (PREP_FOLD + 24 * 14)        // +336 = 1592
#define PREP_X    (PREP_W + 768)               // +768 = 2360

// ---------------------------------------------------------------------------
// Scratch (all __device__ globals; no allocation)
// ---------------------------------------------------------------------------
__device__ float g_Upart[NFOLD * HH2];
__device__ __nv_bfloat16 g_xhi[BSROWS * Dd], g_xlo[BSROWS * Dd];
__device__ __nv_bfloat16 g_Wthi[NPW * Dd], g_Wtlo[NPW * Dd];
__device__ __nv_bfloat16 g_Uthi[NPU * KP], g_Utlo[NPU * KP];
__device__ __nv_bfloat16 g_hhi[BSROWS * KP], g_hlo[BSROWS * KP];
__device__ __nv_bfloat16 g_thi[BSROWS * KP], g_tlo[BSROWS * KP];
__device__ __nv_bfloat16 g_Mhi[BSROWS * KP], g_Mlo[BSROWS * KP];

__device__ __forceinline__ void bsplit(float v, __nv_bfloat16& h,
                                       __nv_bfloat16& l) {
    h = __float2bfloat16(v);
    l = __float2bfloat16(v - __bfloat162float(h));
}

// ---------------------------------------------------------------------------
// prep_kernel: fold partials  ∪  W transpose+split  ∪  x split.
// ---------------------------------------------------------------------------
__global__ void prep_kernel(const float* __restrict__ U,
                            const float* __restrict__ W_down,
                            const float* __restrict__ Wh,
                            const float* __restrict__ Wt,
                            const float* __restrict__ x) {
    __shared__ float tile[32][33];
    const int bid = blockIdx.x;
    const int t = threadIdx.x;

    if (bid < PREP_FOLD) {
        int p = bid / FOLD_BLKS, blk = bid - p * FOLD_BLKS;
        int idx = blk * 256 + t;
        if (idx >= HH2) return;
        int o0 = p * 25;
        const float* pp = U + (size_t)o0 * HH2 + idx;
        const float* w = W_down + o0;
        float a0 = 0.f, a1 = 0.f, a2 = 0.f, a3 = 0.f, a4 = 0.f;
#pragma unroll
        for (int u = 0; u < 25; u += 5) {
            a0 = fmaf(pp[(size_t)(u + 0) * HH2], __ldg(w + u + 0), a0);
            a1 = fmaf(pp[(size_t)(u + 1) * HH2], __ldg(w + u + 1), a1);
            a2 = fmaf(pp[(size_t)(u + 2) * HH2], __ldg(w + u + 2), a2);
            a3 = fmaf(pp[(size_t)(u + 3) * HH2], __ldg(w + u + 3), a3);
            a4 = fmaf(pp[(size_t)(u + 4) * HH2], __ldg(w + u + 4), a4);
        }
        g_Upart[(size_t)p * HH2 + idx] = ((a0 + a1) + (a2 + a3)) + a4;
    } else if (bid < PREP_W) {
        int sub = bid - PREP_FOLD;
        const int k0 = (sub % 24) * 32, n0 = (sub / 24) * 32;
        const int tx = t & 31, ty = t >> 5;
        const int n = n0 + tx;
#pragma unroll
        for (int j = 0; j < 4; ++j) {
            int k = k0 + ty + j * 8;
            float v = 0.f;
            if (n < Hh) v = Wh[(size_t)k * Hh + n];
            else if (n < 2 * Hh) v = Wt[(size_t)k * Hh + (n - Hh)];
            tile[tx][ty + j * 8] = v;
        }
        __syncthreads();
#pragma unroll
        for (int j = 0; j < 4; ++j) {
            int nn = n0 + ty + j * 8, k = k0 + tx;
            float v = tile[ty + j * 8][tx];
            __nv_bfloat16 h, l;
            bsplit(v, h, l);
            g_Wthi[(size_t)nn * Dd + k] = h;
            g_Wtlo[(size_t)nn * Dd + k] = l;
        }
    } else {
        int i = (bid - PREP_W) * 256 + t;
        const float4* p = (const float4*)x + (size_t)i * 2;
        float4 f0 = p[0], f1 = p[1];
        float v[8] = {f0.x, f0.y, f0.z, f0.w, f1.x, f1.y, f1.z, f1.w};
        union { __nv_bfloat16 h[8]; uint4 u; } H, L;
#pragma unroll
        for (int j = 0; j < 8; ++j) bsplit(v[j], H.h[j], L.h[j]);
        *(uint4*)(g_xhi + (size_t)i * 8) = H.u;
        *(uint4*)(g_xlo + (size_t)i * 8) = L.u;
    }
}

// ---------------------------------------------------------------------------
// MMA / async-copy primitives
// ---------------------------------------------------------------------------
__device__ __forceinline__ void ldsm4(unsigned r[4], unsigned a) {
    asm volatile(
        "ldmatrix.sync.aligned.m8n8.x4.shared.b16 {%0,%1,%2,%3}, [%4];\n"
        : "=r"(r[0]), "=r"(r[1]), "=r"(r[2]), "=r"(r[3])
        : "r"(a));
}
__device__ __forceinline__ void mma_bf16(float c[4], const unsigned a[4],
                                         const unsigned b[2]) {
    asm volatile(
        "mma.sync.aligned.m16n8k16.row.col.f32.bf16.bf16.f32 "
        "{%0,%1,%2,%3}, {%4,%5,%6,%7}, {%8,%9}, {%0,%1,%2,%3};\n"
        : "+f"(c[0]), "+f"(c[1]), "+f"(c[2]), "+f"(c[3])
        : "r"(a[0]), "r"(a[1]), "r"(a[2]), "r"(a[3]), "r"(b[0]), "r"(b[1]));
}
__device__ __forceinline__ void cp16(unsigned saddr, const void* g) {
    asm volatile("cp.async.cg.shared.global [%0], [%1], 16;\n" ::"r"(saddr),
                 "l"(g));
}
#define CP_COMMIT() asm volatile("cp.async.commit_group;\n" ::: "memory")
#define CP_WAIT3()  asm volatile("cp.async.wait_group 3;\n" ::: "memory")

// XOR swizzle for 64B rows.
__device__ __forceinline__ unsigned swz(int row, int c) {
    return (unsigned)(row * 64 + ((c ^ ((row >> 1) & 3)) << 4));
}

// ---------------------------------------------------------------------------
// Shared GEMM body: bf16x3 MMA, 5-stage cp.async pipeline (3 tiles in flight).
// A planes [m][k] (lda), B planes [n][k] (ldb); all zero-padded.
// ---------------------------------------------------------------------------
#define GEMM_SMEM (5 * 16384)
template <int MODE>
__device__ __forceinline__ void gemm_body(
    int m0, int n0, int bz, unsigned char* smem,
    const __nv_bfloat16* Ahi, const __nv_bfloat16* Alo, int lda,
    const __nv_bfloat16* Bhi, const __nv_bfloat16* Blo, int ldb, int ktiles,
    const float* bias_h, const float* bias_t, float* outf,
    const float* bdown) {
    constexpr int BM = 64;
    constexpr int ABYTES = BM * 64;
    constexpr int BBYTES = 64 * 64;
    constexpr int STAGE = 2 * ABYTES + 2 * BBYTES;  // 16384
    constexpr int NSTAGE = 5;

    const int t = threadIdx.x;
    const int lane = t & 31, warp = t >> 5;
    const int wm = (warp & 1) * 32, wn = (warp >> 1) * 16;

    if (MODE == 2) {
        size_t ofs = (size_t)bz * SQ;
        Ahi += ofs * lda; Alo += ofs * lda;
        Bhi += ofs * ldb; Blo += ofs * ldb;
    }

    const __nv_bfloat16* aptr[2];
    unsigned aoff[2];
#pragma unroll
    for (int i = 0; i < 2; ++i) {
        int ca = t + i * 256;
        int pl = ca / (BM * 4);
        int rem = ca - pl * (BM * 4);
        int row = rem >> 2, c = rem & 3;
        aptr[i] = (pl ? Alo : Ahi) + (size_t)(m0 + row) * lda + c * 8;
        aoff[i] = pl * ABYTES + swz(row, c);
    }
    const __nv_bfloat16* bptr[2];
    unsigned boff[2];
#pragma unroll
    for (int i = 0; i < 2; ++i) {
        int cb = t + i * 256;
        int pl = cb >> 8;
        int rem = cb & 255;
        int row = rem >> 2, c = rem & 3;
        bptr[i] = (pl ? Blo : Bhi) + (size_t)(n0 + row) * ldb + c * 8;
        boff[i] = 2 * ABYTES + pl * BBYTES + swz(row, c);
    }

    const unsigned sbase = (unsigned)__cvta_generic_to_shared(smem);

    auto issue = [&](int kt) {
        unsigned so = sbase + (kt % NSTAGE) * STAGE;
#pragma unroll
        for (int i = 0; i < 2; ++i) cp16(so + aoff[i], aptr[i] + kt * 32);
#pragma unroll
        for (int i = 0; i < 2; ++i) cp16(so + boff[i], bptr[i] + kt * 32);
    };

    float acc[2][2][4];
#pragma unroll
    for (int mi = 0; mi < 2; ++mi)
#pragma unroll
        for (int ni = 0; ni < 2; ++ni)
#pragma unroll
            for (int r = 0; r < 4; ++r) acc[mi][ni][r] = 0.f;

    auto compute = [&](int stg) {
        unsigned bb = sbase + stg * STAGE;
#pragma unroll
        for (int s = 0; s < 2; ++s) {
            unsigned ah[2][4], al[2][4], bh2[2][2], bl2[2][2];
            {
                int row0 = wm + (lane & 15);
                int c = 2 * s + (lane >> 4);
#pragma unroll
                for (int mi = 0; mi < 2; ++mi) {
                    unsigned sa = swz(row0 + mi * 16, c);
                    ldsm4(ah[mi], bb + sa);
                    ldsm4(al[mi], bb + ABYTES + sa);
                }
            }
            {
                int rbase = wn + (lane & 7) + ((lane >> 4) << 3);
                int c = 2 * s + ((lane >> 3) & 1);
                unsigned sb = swz(rbase, c);
                unsigned tmp[4];
                ldsm4(tmp, bb + 2 * ABYTES + sb);
                bh2[0][0] = tmp[0]; bh2[0][1] = tmp[1];
                bh2[1][0] = tmp[2]; bh2[1][1] = tmp[3];
                ldsm4(tmp, bb + 2 * ABYTES + BBYTES + sb);
                bl2[0][0] = tmp[0]; bl2[0][1] = tmp[1];
                bl2[1][0] = tmp[2]; bl2[1][1] = tmp[3];
            }
#pragma unroll
            for (int mi = 0; mi < 2; ++mi)
#pragma unroll
                for (int ni = 0; ni < 2; ++ni)
                    mma_bf16(acc[mi][ni], ah[mi], bh2[ni]);
#pragma unroll
            for (int mi = 0; mi < 2; ++mi)
#pragma unroll
                for (int ni = 0; ni < 2; ++ni)
                    mma_bf16(acc[mi][ni], ah[mi], bl2[ni]);
#pragma unroll
            for (int mi = 0; mi < 2; ++mi)
#pragma unroll
                for (int ni = 0; ni < 2; ++ni)
                    mma_bf16(acc[mi][ni], al[mi], bh2[ni]);
        }
    };

    // prologue: 4 stages in flight (ktiles >= 4 always: 7 or 24)
    issue(0); CP_COMMIT();
    issue(1); CP_COMMIT();
    issue(2); CP_COMMIT();
    issue(3); CP_COMMIT();
    CP_WAIT3();          // stage 0 complete
    __syncthreads();

#pragma unroll 1
    for (int kt = 0; kt < ktiles; ++kt) {
        compute(kt % NSTAGE);
        if (kt + 4 < ktiles) issue(kt + 4);
        CP_COMMIT();     // (possibly empty group keeps the count aligned)
        CP_WAIT3();      // stage kt+1 complete
        __syncthreads();
    }

    const float rs = 0.070710678118654752f;
    float bd = 0.f;
    if (MODE == 2) bd = __ldg(bdown);

#pragma unroll
    for (int mi = 0; mi < 2; ++mi) {
#pragma unroll
        for (int ni = 0; ni < 2; ++ni) {
#pragma unroll
            for (int rp = 0; rp < 2; ++rp) {
                int row = m0 + wm + mi * 16 + (lane >> 2) + rp * 8;
                int col = n0 + wn + ni * 8 + 2 * (lane & 3);
                float v0 = acc[mi][ni][rp * 2];
                float v1 = acc[mi][ni][rp * 2 + 1];
                if (MODE == 0) {
                    if (col < Hh) {
                        v0 = fmaxf(v0 + __ldg(&bias_h[col]), 0.f);
                        v1 = fmaxf(v1 + __ldg(&bias_h[col + 1]), 0.f);
                        __nv_bfloat16 h0, l0, h1, l1;
                        bsplit(v0, h0, l0);
                        bsplit(v1, h1, l1);
                        size_t o = (size_t)row * KP + col;
                        *(__nv_bfloat162*)(g_hhi + o) = __halves2bfloat162(h0, h1);
                        *(__nv_bfloat162*)(g_hlo + o) = __halves2bfloat162(l0, l1);
                    } else {
                        int c = col - Hh;
                        if (c < KP) {
                            if (col < 2 * Hh) {
                                v0 = fmaxf(v0 + __ldg(&bias_t[c]), 0.f);
                                v1 = fmaxf(v1 + __ldg(&bias_t[c + 1]), 0.f);
                            } else {
                                v0 = 0.f;
                                v1 = 0.f;
                            }
                            __nv_bfloat16 h0, l0, h1, l1;
                            bsplit(v0, h0, l0);
                            bsplit(v1, h1, l1);
                            size_t o = (size_t)row * KP + c;
                            *(__nv_bfloat162*)(g_thi + o) =
                                __halves2bfloat162(h0, h1);
                            *(__nv_bfloat162*)(g_tlo + o) =
                                __halves2bfloat162(l0, l1);
                        }
                    }
                } else if (MODE == 1) {
                    if (col < KP) {
                        if (col >= Hh) { v0 = 0.f; v1 = 0.f; }
                        __nv_bfloat16 h0, l0, h1, l1;
                        bsplit(v0, h0, l0);
                        bsplit(v1, h1, l1);
                        size_t o = (size_t)row * KP + col;
                        *(__nv_bfloat162*)(g_Mhi + o) = __halves2bfloat162(h0, h1);
                        *(__nv_bfloat162*)(g_Mlo + o) = __halves2bfloat162(l0, l1);
                    }
                } else {
                    float2 o;
                    o.x = (v0 + bd) * rs;
                    o.y = (v1 + bd) * rs;
                    *(float2*)(outf + (size_t)bz * SQ * SQ +
                               (size_t)row * SQ + col) = o;
                }
            }
        }
    }
}

// ---------------------------------------------------------------------------
// proj ∪ split_ut_pad in one launch.
// ---------------------------------------------------------------------------
__global__ __launch_bounds__(256) void proj_ut_kernel(
    const __nv_bfloat16* __restrict__ Ahi, const __nv_bfloat16* __restrict__ Alo,
    const __nv_bfloat16* __restrict__ Bhi, const __nv_bfloat16* __restrict__ Blo,
    const float* __restrict__ bias_h, const float* __restrict__ bias_t) {
    extern __shared__ __align__(16) unsigned char smem[];
    __shared__ float tile[32][33];
    const int bid = blockIdx.x;
    const int t = threadIdx.x;

    if (bid < 224) {
        gemm_body<0>((bid / 7) * 64, (bid % 7) * 64, 0, smem, Ahi, Alo, Dd,
                     Bhi, Blo, Dd, Dd / 32, bias_h, bias_t, nullptr, nullptr);
        return;
    }

    int sub = bid - 224;
    int bx = sub % 7, by = sub / 7;
    if (by == 8) {
        const uint4 z = make_uint4(0, 0, 0, 0);
        for (int i = bx * 256 + t; i < BSROWS * 3; i += 7 * 256) {
            int row = i / 3, c = Hh + (i % 3) * 8;
            *(uint4*)(g_hhi + (size_t)row * KP + c) = z;
            *(uint4*)(g_hlo + (size_t)row * KP + c) = z;
        }
        return;
    }
    const int k0 = bx * 32, n0 = by * 32;
    const int tx = t & 31, ty = t >> 5;
    const int n = n0 + tx;
#pragma unroll
    for (int j = 0; j < 4; ++j) {
        int k = k0 + ty + j * 8;
        float v = 0.f;
        if (n < Hh && k < Hh) {
            size_t o = (size_t)k * Hh + n;
#pragma unroll
            for (int p = 0; p < NFOLD; ++p) v += g_Upart[p * HH2 + o];
        }
        tile[tx][ty + j * 8] = v;
    }
    __syncthreads();
#pragma unroll
    for (int j = 0; j < 4; ++j) {
        int nn = n0 + ty + j * 8, k = k0 + tx;
        float v = tile[ty + j * 8][tx];
        __nv_bfloat16 h, l;
        bsplit(v, h, l);
        g_Uthi[(size_t)nn * KP + k] = h;
        g_Utlo[(size_t)nn * KP + k] = l;
    }
}

// ---------------------------------------------------------------------------
// gemm_m / scores launches
// ---------------------------------------------------------------------------
template <int MODE>
__global__ __launch_bounds__(256) void mma_gemm_kernel(
    const __nv_bfloat16* __restrict__ Ahi, const __nv_bfloat16* __restrict__ Alo,
    int lda,
    const __nv_bfloat16* __restrict__ Bhi, const __nv_bfloat16* __restrict__ Blo,
    int ldb, int ktiles, float* __restrict__ outf,
    const float* __restrict__ bdown) {
    extern __shared__ __align__(16) unsigned char smem[];
    gemm_body<MODE>(blockIdx.y * 64, blockIdx.x * 64, blockIdx.z, smem, Ahi,
                    Alo, lda, Bhi, Blo, ldb, ktiles, nullptr, nullptr, outf,
                    bdown);
}

// ---------------------------------------------------------------------------
// Inputs (metadata order): x, W_head, b_head, W_tail, b_tail, U, W_down, b_down
// ---------------------------------------------------------------------------
extern "C" void kernel_launch(void* const* d_in, const int* in_sizes, int n_in,
                              void* d_out, int out_size) {
    const float* x      = (const float*)d_in[0];
    const float* W_head = (const float*)d_in[1];
    const float* b_head = (const float*)d_in[2];
    const float* W_tail = (const float*)d_in[3];
    const float* b_tail = (const float*)d_in[4];
    const float* U      = (const float*)d_in[5];
    const float* W_down = (const float*)d_in[6];
    const float* b_down = (const float*)d_in[7];
    float* out = (float*)d_out;

    static __nv_bfloat16 *p_xhi, *p_xlo, *p_Wthi, *p_Wtlo, *p_Uthi, *p_Utlo;
    static __nv_bfloat16 *p_hhi, *p_hlo, *p_thi, *p_tlo, *p_Mhi, *p_Mlo;
    static bool init = false;
    if (!init) {
        cudaGetSymbolAddress((void**)&p_xhi, g_xhi);
        cudaGetSymbolAddress((void**)&p_xlo, g_xlo);
        cudaGetSymbolAddress((void**)&p_Wthi, g_Wthi);
        cudaGetSymbolAddress((void**)&p_Wtlo, g_Wtlo);
        cudaGetSymbolAddress((void**)&p_Uthi, g_Uthi);
        cudaGetSymbolAddress((void**)&p_Utlo, g_Utlo);
        cudaGetSymbolAddress((void**)&p_hhi, g_hhi);
        cudaGetSymbolAddress((void**)&p_hlo, g_hlo);
        cudaGetSymbolAddress((void**)&p_thi, g_thi);
        cudaGetSymbolAddress((void**)&p_tlo, g_tlo);
        cudaGetSymbolAddress((void**)&p_Mhi, g_Mhi);
        cudaGetSymbolAddress((void**)&p_Mlo, g_Mlo);
        cudaFuncSetAttribute(proj_ut_kernel,
                             cudaFuncAttributeMaxDynamicSharedMemorySize,
                             GEMM_SMEM);
        cudaFuncSetAttribute(mma_gemm_kernel<1>,
                             cudaFuncAttributeMaxDynamicSharedMemorySize,
                             GEMM_SMEM);
        cudaFuncSetAttribute(mma_gemm_kernel<2>,
                             cudaFuncAttributeMaxDynamicSharedMemorySize,
                             GEMM_SMEM);
        init = true;
    }

    // 1) all independent prep in ONE launch (fold ∪ split_w ∪ split_x)
    prep_kernel<<<PREP_X, 256>>>(U, W_down, W_head, W_tail, x);

    // 2) proj ∪ (Ut transpose/split + head pads)
    proj_ut_kernel<<<224 + 63, 256, GEMM_SMEM>>>(p_xhi, p_xlo, p_Wthi,
                                                 p_Wtlo, b_head, b_tail);

    // 3) M = head @ Ueff
    mma_gemm_kernel<1><<<dim3(NPU / 64, BSROWS / 64), 256, GEMM_SMEM>>>(
        p_hhi, p_hlo, KP, p_Uthi, p_Utlo, KP, KP / 32, nullptr, nullptr);

    // 4) scores[b] = (M_b @ tail_b^T + b_down) / sqrt(200)
    mma_gemm_kernel<2><<<dim3(SQ / 64, SQ / 64, NB), 256, GEMM_SMEM>>>(
        p_Mhi, p_Mlo, KP, p_thi, p_tlo, KP, KP / 32, out, b_down);
}